// round 9
// baseline (speedup 1.0000x reference)
#include <cuda_runtime.h>
#include <cuda_fp16.h>
#include <math.h>

// ---------------------------------------------------------------------------
// GaussianSplatRenderer3D — B=4, N=32768, H=W=512, k=11 (121 taps)
// ONE persistent kernel, 148 co-resident blocks, manual grid barrier.
// Pipeline: zero(b0) | [splat(b) + zero(b+1) + normalize(b-1)] | norm(B-1).
// Normalize/zero hide under the RED-wavefront-bound splat of the next batch.
// Splat: ONE red.global.add.noftz.v4.f16x2 per tap.
// ---------------------------------------------------------------------------

#define KTAP 11
#define MAXPIX (4 * 512 * 512)
#define NBLK 148
#define NTHR 256

static __device__ uint4 g_acc[MAXPIX];   // 8 x f16 per pixel
static __device__ unsigned g_cnt = 0;    // barrier arrive counter
static __device__ unsigned g_gen = 0;    // barrier generation (monotonic)

// Grid-wide barrier: safe because grid==NBLK co-resident blocks.
// Release: threadfence before arrive (makes REDs/stores visible).
// Acquire: threadfence after spin.
__device__ __forceinline__ void grid_sync(unsigned& target) {
    __syncthreads();
    if (threadIdx.x == 0) {
        __threadfence();
        unsigned t = atomicAdd(&g_cnt, 1u);
        if (t == NBLK - 1u) {
            g_cnt = 0u;
            __threadfence();
            atomicAdd(&g_gen, 1u);
        }
        while (atomicAdd(&g_gen, 0u) < target) __nanosleep(64);
        __threadfence();
    }
    __syncthreads();
    ++target;
}

__device__ __forceinline__ void zero_batch(int b, int HW, int tid, int total) {
    uint4 z = make_uint4(0u, 0u, 0u, 0u);
    int base = b * HW;
    for (int i = tid; i < HW; i += total)
        g_acc[base + i] = z;
}

__device__ __forceinline__ void splat_batch(
    const float* __restrict__ pos, const float* __restrict__ cov,
    const float* __restrict__ rgb, const float* __restrict__ opa,
    const float* __restrict__ Km,  const float* __restrict__ Rm,
    const float* __restrict__ tv,  int b, int N, int H, int W,
    int tid, int total)
{
    const float* Kb = Km + 9 * b;
    const float* Rb = Rm + 9 * b;
    const float* tb = tv + 3 * b;

    for (int g = tid; g < N; g += total) {
        int gid = b * N + g;

        float p0 = pos[3 * gid + 0];
        float p1 = pos[3 * gid + 1];
        float p2 = pos[3 * gid + 2];

        // Xc = R @ p + t  (mul/add chain, no FMA contraction — matches XLA dot)
        float X = __fadd_rn(__fadd_rn(__fadd_rn(__fmul_rn(Rb[0], p0), __fmul_rn(Rb[1], p1)),
                                      __fmul_rn(Rb[2], p2)), tb[0]);
        float Y = __fadd_rn(__fadd_rn(__fadd_rn(__fmul_rn(Rb[3], p0), __fmul_rn(Rb[4], p1)),
                                      __fmul_rn(Rb[5], p2)), tb[1]);
        float Z = __fadd_rn(__fadd_rn(__fadd_rn(__fmul_rn(Rb[6], p0), __fmul_rn(Rb[7], p1)),
                                      __fmul_rn(Rb[8], p2)), tb[2]);

        float zs = fmaxf(Z, 1e-6f);
        float xs = __fdiv_rn(X, zs);
        float ys = __fdiv_rn(Y, zs);

        float u = __fadd_rn(__fadd_rn(__fmul_rn(Kb[0], xs), __fmul_rn(Kb[1], ys)), Kb[2]);
        float v = __fadd_rn(__fadd_rn(__fmul_rn(Kb[3], xs), __fmul_rn(Kb[4], ys)), Kb[5]);
        float fx = Kb[0];
        float fy = Kb[4];

        float sxx = cov[3 * gid + 0];
        float syy = cov[3 * gid + 1];
        float sx = __fdiv_rn(__fmul_rn(__fsqrt_rn(fmaxf(sxx, 1e-9f)), fx), zs);
        float sy = __fdiv_rn(__fmul_rn(__fsqrt_rn(fmaxf(syy, 1e-9f)), fy), zs);

        float o  = opa[gid];
        float cr = rgb[3 * gid + 0];
        float cg = rgb[3 * gid + 1];
        float cb = rgb[3 * gid + 2];

        __half2 h_rg = __floats2half2_rn(cr, cg);
        __half2 h_bz = __floats2half2_rn(cb, Z);

        float isx = __fdiv_rn(1.f, fmaxf(sx, 1e-6f));
        float isy = __fdiv_rn(1.f, fmaxf(sy, 1e-6f));

        float wxm[KTAP], wyo[KTAP];
        int   xoff[KTAP], yrow[KTAP];
#pragma unroll
        for (int i = 0; i < KTAP; ++i) {
            float off = (float)(i - KTAP / 2);
            float gx = __fmul_rn(off, isx);
            float gy = __fmul_rn(off, isy);
            float ewx = __expf(-0.5f * __fmul_rn(gx, gx));
            float ewy = __expf(-0.5f * __fmul_rn(gy, gy));
            int px = __float2int_rn(__fadd_rn(u, __fmul_rn(off, sx)));
            int py = __float2int_rn(__fadd_rn(v, __fmul_rn(off, sy)));
            bool okx = (px >= 0) & (px < W);
            bool oky = (py >= 0) & (py < H);
            wxm[i] = okx ? ewx : 0.f;
            wyo[i] = oky ? __fmul_rn(ewy, o) : 0.f;
            xoff[i] = px * 16;
            yrow[i] = py * W * 16;
        }

        char* baseb = (char*)g_acc + (size_t)b * (H * W) * 16;
#pragma unroll
        for (int j = 0; j < KTAP; ++j) {
            float wj = wyo[j];
            if (wj == 0.f) continue;
            char* rowp = baseb + yrow[j];
#pragma unroll
            for (int i = 0; i < KTAP; ++i) {
                float wi = wxm[i];
                if (wi == 0.f) continue;
                float a = __fmul_rn(wi, wj);
                __half2 a2 = __floats2half2_rn(a, a);
                __half2 v0 = __hmul2(h_rg, a2);   // (r*a, g*a)
                __half2 v1 = __hmul2(h_bz, a2);   // (b*a, z*a)
                unsigned r0 = *(unsigned*)&v0;
                unsigned r1 = *(unsigned*)&v1;
                unsigned r2 = *(unsigned*)&a2;    // (a, a) — free
                char* dst = rowp + xoff[i];
                asm volatile("red.global.add.noftz.v4.f16x2 [%0], {%1, %2, %3, %4};"
                             :: "l"(dst), "r"(r0), "r"(r1), "r"(r2), "r"(0u)
                             : "memory");
            }
        }
    }
}

__device__ __forceinline__ void normalize_batch(
    float* __restrict__ out, int b, int B, int HW, int tid, int total)
{
    int nquad = HW >> 2;
    float* zbase = out + (size_t)B * 3 * HW + (size_t)b * HW;
    float* cbase = out + (size_t)b * 3 * HW;
    for (int q = tid; q < nquad; q += total) {
        int i0 = q << 2;
        int gbase = b * HW + i0;
        uint4 a0 = g_acc[gbase + 0];
        uint4 a1 = g_acc[gbase + 1];
        uint4 a2 = g_acc[gbase + 2];
        uint4 a3 = g_acc[gbase + 3];

        float4 r4, g4, b4, z4;
        {
            float2 f0 = __half22float2(*(__half2*)&a0.x);
            float2 f1 = __half22float2(*(__half2*)&a0.y);
            float den = fmaxf(__low2float(*(__half2*)&a0.z), 1e-6f);
            float inv; asm("rcp.approx.f32 %0, %1;" : "=f"(inv) : "f"(den));
            r4.x = f0.x * inv; g4.x = f0.y * inv; b4.x = f1.x * inv; z4.x = f1.y * inv;
        }
        {
            float2 f0 = __half22float2(*(__half2*)&a1.x);
            float2 f1 = __half22float2(*(__half2*)&a1.y);
            float den = fmaxf(__low2float(*(__half2*)&a1.z), 1e-6f);
            float inv; asm("rcp.approx.f32 %0, %1;" : "=f"(inv) : "f"(den));
            r4.y = f0.x * inv; g4.y = f0.y * inv; b4.y = f1.x * inv; z4.y = f1.y * inv;
        }
        {
            float2 f0 = __half22float2(*(__half2*)&a2.x);
            float2 f1 = __half22float2(*(__half2*)&a2.y);
            float den = fmaxf(__low2float(*(__half2*)&a2.z), 1e-6f);
            float inv; asm("rcp.approx.f32 %0, %1;" : "=f"(inv) : "f"(den));
            r4.z = f0.x * inv; g4.z = f0.y * inv; b4.z = f1.x * inv; z4.z = f1.y * inv;
        }
        {
            float2 f0 = __half22float2(*(__half2*)&a3.x);
            float2 f1 = __half22float2(*(__half2*)&a3.y);
            float den = fmaxf(__low2float(*(__half2*)&a3.z), 1e-6f);
            float inv; asm("rcp.approx.f32 %0, %1;" : "=f"(inv) : "f"(den));
            r4.w = f0.x * inv; g4.w = f0.y * inv; b4.w = f1.x * inv; z4.w = f1.y * inv;
        }

        *(float4*)(cbase + i0)          = r4;
        *(float4*)(cbase + HW + i0)     = g4;
        *(float4*)(cbase + 2 * HW + i0) = b4;
        *(float4*)(zbase + i0)          = z4;
    }
}

__global__ void __launch_bounds__(NTHR)
render_kernel(const float* __restrict__ pos, const float* __restrict__ cov,
              const float* __restrict__ rgb, const float* __restrict__ opa,
              const float* __restrict__ Km,  const float* __restrict__ Rm,
              const float* __restrict__ tv,  float* __restrict__ out,
              int B, int N, int H, int W)
{
    int tid   = blockIdx.x * blockDim.x + threadIdx.x;
    int total = NBLK * NTHR;
    int HW    = H * W;

    unsigned target = g_gen + 1u;   // read before first arrive (uniform)

    zero_batch(0, HW, tid, total);
    grid_sync(target);

    for (int b = 0; b < B; ++b) {
        splat_batch(pos, cov, rgb, opa, Km, Rm, tv, b, N, H, W, tid, total);
        if (b + 1 < B) zero_batch(b + 1, HW, tid, total);
        if (b > 0)     normalize_batch(out, b - 1, B, HW, tid, total);
        grid_sync(target);
    }

    normalize_batch(out, B - 1, B, HW, tid, total);
}

extern "C" void kernel_launch(void* const* d_in, const int* in_sizes, int n_in,
                              void* d_out, int out_size)
{
    const float* pos = (const float*)d_in[0];
    const float* cov = (const float*)d_in[1];
    const float* rgb = (const float*)d_in[2];
    const float* opa = (const float*)d_in[3];
    const float* Km  = (const float*)d_in[4];
    const float* Rm  = (const float*)d_in[5];
    const float* tv  = (const float*)d_in[6];

    int B  = in_sizes[4] / 9;
    int N  = in_sizes[0] / (3 * B);
    int HW = out_size / (4 * B);
    int W  = (int)(sqrt((double)HW) + 0.5);
    int H  = HW / W;

    render_kernel<<<NBLK, NTHR>>>(pos, cov, rgb, opa, Km, Rm, tv,
                                  (float*)d_out, B, N, H, W);
}

// round 10
// speedup vs baseline: 1.0982x; 1.0982x over previous
#include <cuda_runtime.h>
#include <cuda_fp16.h>
#include <math.h>

// ---------------------------------------------------------------------------
// GaussianSplatRenderer3D — B=4, N=32768, H=W=512, k=11 (121 taps)
// Persistent kernel, 444 blocks (3/SM guaranteed), WARP-SPECIALIZED pipeline:
//   step b: warps 0-2 splat(b) | warp 3 zero(b+1) | warps 4-7 normalize(b-1)
// True overlap: zero/normalize execute on warps concurrent with the
// RED-wavefront-bound splat. Splat: ONE red.global.add.noftz.v4.f16x2 / tap.
// ---------------------------------------------------------------------------

#define KTAP 11
#define MAXPIX (4 * 512 * 512)
#define NBLK 444
#define NTHR 256

// role layout within a 256-thread block
#define SPLAT_THR 96     // warps 0-2
#define ZERO_BASE 96     // warp 3
#define ZERO_THR  32
#define NORM_BASE 128    // warps 4-7
#define NORM_THR  128

static __device__ uint4 g_acc[MAXPIX];   // 8 x f16 per pixel
static __device__ unsigned g_cnt = 0;
static __device__ unsigned g_gen = 0;

__device__ __forceinline__ void grid_sync(unsigned& target) {
    __syncthreads();
    if (threadIdx.x == 0) {
        __threadfence();
        unsigned t = atomicAdd(&g_cnt, 1u);
        if (t == NBLK - 1u) {
            g_cnt = 0u;
            __threadfence();
            atomicAdd(&g_gen, 1u);
        }
        while (atomicAdd(&g_gen, 0u) < target) __nanosleep(64);
        __threadfence();
    }
    __syncthreads();
    ++target;
}

// Zero one batch with `nw` workers, worker id `wid` (coalesced block-major).
__device__ __forceinline__ void zero_batch(int b, int HW, int wid, int nw) {
    uint4 z = make_uint4(0u, 0u, 0u, 0u);
    int base = b * HW;
    for (int i = wid; i < HW; i += nw)
        g_acc[base + i] = z;
}

__device__ __forceinline__ void splat_one(
    const float* __restrict__ pos, const float* __restrict__ cov,
    const float* __restrict__ rgb, const float* __restrict__ opa,
    const float* __restrict__ Km,  const float* __restrict__ Rm,
    const float* __restrict__ tv,  int b, int gid, int H, int W)
{
    const float* Kb = Km + 9 * b;
    const float* Rb = Rm + 9 * b;
    const float* tb = tv + 3 * b;

    float p0 = pos[3 * gid + 0];
    float p1 = pos[3 * gid + 1];
    float p2 = pos[3 * gid + 2];

    // Xc = R @ p + t  (mul/add chain, no FMA contraction — matches XLA dot)
    float X = __fadd_rn(__fadd_rn(__fadd_rn(__fmul_rn(Rb[0], p0), __fmul_rn(Rb[1], p1)),
                                  __fmul_rn(Rb[2], p2)), tb[0]);
    float Y = __fadd_rn(__fadd_rn(__fadd_rn(__fmul_rn(Rb[3], p0), __fmul_rn(Rb[4], p1)),
                                  __fmul_rn(Rb[5], p2)), tb[1]);
    float Z = __fadd_rn(__fadd_rn(__fadd_rn(__fmul_rn(Rb[6], p0), __fmul_rn(Rb[7], p1)),
                                  __fmul_rn(Rb[8], p2)), tb[2]);

    float zs = fmaxf(Z, 1e-6f);
    float xs = __fdiv_rn(X, zs);
    float ys = __fdiv_rn(Y, zs);

    float u = __fadd_rn(__fadd_rn(__fmul_rn(Kb[0], xs), __fmul_rn(Kb[1], ys)), Kb[2]);
    float v = __fadd_rn(__fadd_rn(__fmul_rn(Kb[3], xs), __fmul_rn(Kb[4], ys)), Kb[5]);
    float fx = Kb[0];
    float fy = Kb[4];

    float sxx = cov[3 * gid + 0];
    float syy = cov[3 * gid + 1];
    float sx = __fdiv_rn(__fmul_rn(__fsqrt_rn(fmaxf(sxx, 1e-9f)), fx), zs);
    float sy = __fdiv_rn(__fmul_rn(__fsqrt_rn(fmaxf(syy, 1e-9f)), fy), zs);

    float o  = opa[gid];
    float cr = rgb[3 * gid + 0];
    float cg = rgb[3 * gid + 1];
    float cb = rgb[3 * gid + 2];

    __half2 h_rg = __floats2half2_rn(cr, cg);
    __half2 h_bz = __floats2half2_rn(cb, Z);

    float isx = __fdiv_rn(1.f, fmaxf(sx, 1e-6f));
    float isy = __fdiv_rn(1.f, fmaxf(sy, 1e-6f));

    float wxm[KTAP], wyo[KTAP];
    int   xoff[KTAP], yrow[KTAP];
#pragma unroll
    for (int i = 0; i < KTAP; ++i) {
        float off = (float)(i - KTAP / 2);
        float gx = __fmul_rn(off, isx);
        float gy = __fmul_rn(off, isy);
        float ewx = __expf(-0.5f * __fmul_rn(gx, gx));
        float ewy = __expf(-0.5f * __fmul_rn(gy, gy));
        int px = __float2int_rn(__fadd_rn(u, __fmul_rn(off, sx)));
        int py = __float2int_rn(__fadd_rn(v, __fmul_rn(off, sy)));
        bool okx = (px >= 0) & (px < W);
        bool oky = (py >= 0) & (py < H);
        wxm[i] = okx ? ewx : 0.f;
        wyo[i] = oky ? __fmul_rn(ewy, o) : 0.f;
        xoff[i] = px * 16;
        yrow[i] = py * W * 16;
    }

    char* baseb = (char*)g_acc + (size_t)b * (H * W) * 16;
#pragma unroll
    for (int j = 0; j < KTAP; ++j) {
        float wj = wyo[j];
        if (wj == 0.f) continue;
        char* rowp = baseb + yrow[j];
#pragma unroll
        for (int i = 0; i < KTAP; ++i) {
            float wi = wxm[i];
            if (wi == 0.f) continue;
            float a = __fmul_rn(wi, wj);
            __half2 a2 = __floats2half2_rn(a, a);
            __half2 v0 = __hmul2(h_rg, a2);   // (r*a, g*a)
            __half2 v1 = __hmul2(h_bz, a2);   // (b*a, z*a)
            unsigned r0 = *(unsigned*)&v0;
            unsigned r1 = *(unsigned*)&v1;
            unsigned r2 = *(unsigned*)&a2;    // (a, a) — free
            char* dst = rowp + xoff[i];
            asm volatile("red.global.add.noftz.v4.f16x2 [%0], {%1, %2, %3, %4};"
                         :: "l"(dst), "r"(r0), "r"(r1), "r"(r2), "r"(0u)
                         : "memory");
        }
    }
}

// Normalize one batch with `nw` workers (coalesced block-major quads).
__device__ __forceinline__ void normalize_batch(
    float* __restrict__ out, int b, int B, int HW, int wid, int nw)
{
    int nquad = HW >> 2;
    float* zbase = out + (size_t)B * 3 * HW + (size_t)b * HW;
    float* cbase = out + (size_t)b * 3 * HW;
    for (int q = wid; q < nquad; q += nw) {
        int i0 = q << 2;
        int gbase = b * HW + i0;
        uint4 a0 = g_acc[gbase + 0];
        uint4 a1 = g_acc[gbase + 1];
        uint4 a2 = g_acc[gbase + 2];
        uint4 a3 = g_acc[gbase + 3];

        float4 r4, g4, b4, z4;
        {
            float2 f0 = __half22float2(*(__half2*)&a0.x);
            float2 f1 = __half22float2(*(__half2*)&a0.y);
            float den = fmaxf(__low2float(*(__half2*)&a0.z), 1e-6f);
            float inv; asm("rcp.approx.f32 %0, %1;" : "=f"(inv) : "f"(den));
            r4.x = f0.x * inv; g4.x = f0.y * inv; b4.x = f1.x * inv; z4.x = f1.y * inv;
        }
        {
            float2 f0 = __half22float2(*(__half2*)&a1.x);
            float2 f1 = __half22float2(*(__half2*)&a1.y);
            float den = fmaxf(__low2float(*(__half2*)&a1.z), 1e-6f);
            float inv; asm("rcp.approx.f32 %0, %1;" : "=f"(inv) : "f"(den));
            r4.y = f0.x * inv; g4.y = f0.y * inv; b4.y = f1.x * inv; z4.y = f1.y * inv;
        }
        {
            float2 f0 = __half22float2(*(__half2*)&a2.x);
            float2 f1 = __half22float2(*(__half2*)&a2.y);
            float den = fmaxf(__low2float(*(__half2*)&a2.z), 1e-6f);
            float inv; asm("rcp.approx.f32 %0, %1;" : "=f"(inv) : "f"(den));
            r4.z = f0.x * inv; g4.z = f0.y * inv; b4.z = f1.x * inv; z4.z = f1.y * inv;
        }
        {
            float2 f0 = __half22float2(*(__half2*)&a3.x);
            float2 f1 = __half22float2(*(__half2*)&a3.y);
            float den = fmaxf(__low2float(*(__half2*)&a3.z), 1e-6f);
            float inv; asm("rcp.approx.f32 %0, %1;" : "=f"(inv) : "f"(den));
            r4.w = f0.x * inv; g4.w = f0.y * inv; b4.w = f1.x * inv; z4.w = f1.y * inv;
        }

        *(float4*)(cbase + i0)          = r4;
        *(float4*)(cbase + HW + i0)     = g4;
        *(float4*)(cbase + 2 * HW + i0) = b4;
        *(float4*)(zbase + i0)          = z4;
    }
}

__global__ void __launch_bounds__(NTHR, 3)
render_kernel(const float* __restrict__ pos, const float* __restrict__ cov,
              const float* __restrict__ rgb, const float* __restrict__ opa,
              const float* __restrict__ Km,  const float* __restrict__ Rm,
              const float* __restrict__ tv,  float* __restrict__ out,
              int B, int N, int H, int W)
{
    int tx  = threadIdx.x;
    int bx  = blockIdx.x;
    int gid = bx * NTHR + tx;
    int HW  = H * W;

    unsigned target = g_gen + 1u;

    // Prologue: all threads zero batch 0 (coalesced).
    zero_batch(0, HW, gid, NBLK * NTHR);
    grid_sync(target);

    for (int b = 0; b < B; ++b) {
        if (tx < SPLAT_THR) {
            // splat role: block-cyclic gaussian -> every SM carries ~equal REDs
            int g = tx * NBLK + bx;
            if (g < N)
                splat_one(pos, cov, rgb, opa, Km, Rm, tv, b, b * N + g, H, W);
        } else if (tx < NORM_BASE) {
            if (b + 1 < B) {
                int wid = bx * ZERO_THR + (tx - ZERO_BASE);
                zero_batch(b + 1, HW, wid, NBLK * ZERO_THR);
            }
        } else {
            if (b > 0) {
                int wid = bx * NORM_THR + (tx - NORM_BASE);
                normalize_batch(out, b - 1, B, HW, wid, NBLK * NORM_THR);
            }
        }
        grid_sync(target);
    }

    // Tail: all threads normalize the last batch.
    normalize_batch(out, B - 1, B, HW, gid, NBLK * NTHR);
}

extern "C" void kernel_launch(void* const* d_in, const int* in_sizes, int n_in,
                              void* d_out, int out_size)
{
    const float* pos = (const float*)d_in[0];
    const float* cov = (const float*)d_in[1];
    const float* rgb = (const float*)d_in[2];
    const float* opa = (const float*)d_in[3];
    const float* Km  = (const float*)d_in[4];
    const float* Rm  = (const float*)d_in[5];
    const float* tv  = (const float*)d_in[6];

    int B  = in_sizes[4] / 9;
    int N  = in_sizes[0] / (3 * B);
    int HW = out_size / (4 * B);
    int W  = (int)(sqrt((double)HW) + 0.5);
    int H  = HW / W;

    render_kernel<<<NBLK, NTHR>>>(pos, cov, rgb, opa, Km, Rm, tv,
                                  (float*)d_out, B, N, H, W);
}

// round 11
// speedup vs baseline: 1.1105x; 1.0112x over previous
#include <cuda_runtime.h>
#include <cuda_fp16.h>
#include <math.h>

// ---------------------------------------------------------------------------
// GaussianSplatRenderer3D — B=4, N=32768, H=W=512, k=11 (121 taps)
// Persistent warp-specialized pipeline, 444 blocks (3/SM):
//   step b: warps 0-2 splat(b) | warp 3 zero(b+1) | warps 4-7 normalize(b-1)
// R10 fix 1: barrier wait polls a VOLATILE LOAD (no atomic-ALU contention).
// R10 fix 2: contiguous per-block gaussian chunks (coalesced input loads).
// Splat: ONE red.global.add.noftz.v4.f16x2 per tap.
// ---------------------------------------------------------------------------

#define KTAP 11
#define MAXPIX (4 * 512 * 512)
#define NBLK 444
#define NTHR 256

#define SPLAT_THR 96     // warps 0-2
#define ZERO_BASE 96     // warp 3
#define ZERO_THR  32
#define NORM_BASE 128    // warps 4-7
#define NORM_THR  128

static __device__ uint4 g_acc[MAXPIX];        // 8 x f16 per pixel
static __device__ unsigned g_cnt = 0;         // barrier arrive counter
static __device__ volatile unsigned g_gen_v = 0;  // barrier generation (poll via LD)

__device__ __forceinline__ void grid_sync(unsigned& target) {
    __syncthreads();
    if (threadIdx.x == 0) {
        __threadfence();
        unsigned t = atomicAdd(&g_cnt, 1u);
        if (t == NBLK - 1u) {
            g_cnt = 0u;          // all arrived; safe to reset before release
            __threadfence();
            g_gen_v = target;    // release (plain volatile store)
        }
        while (g_gen_v < target) __nanosleep(128);   // LOAD poll — no atomic ALU
        __threadfence();
    }
    __syncthreads();
    ++target;
}

__device__ __forceinline__ void zero_batch(int b, int HW, int wid, int nw) {
    uint4 z = make_uint4(0u, 0u, 0u, 0u);
    int base = b * HW;
    for (int i = wid; i < HW; i += nw)
        g_acc[base + i] = z;
}

__device__ __forceinline__ void splat_one(
    const float* __restrict__ pos, const float* __restrict__ cov,
    const float* __restrict__ rgb, const float* __restrict__ opa,
    const float* __restrict__ Km,  const float* __restrict__ Rm,
    const float* __restrict__ tv,  int b, int gid, int H, int W)
{
    const float* Kb = Km + 9 * b;
    const float* Rb = Rm + 9 * b;
    const float* tb = tv + 3 * b;

    float p0 = pos[3 * gid + 0];
    float p1 = pos[3 * gid + 1];
    float p2 = pos[3 * gid + 2];

    // Xc = R @ p + t  (mul/add chain, no FMA contraction — matches XLA dot)
    float X = __fadd_rn(__fadd_rn(__fadd_rn(__fmul_rn(Rb[0], p0), __fmul_rn(Rb[1], p1)),
                                  __fmul_rn(Rb[2], p2)), tb[0]);
    float Y = __fadd_rn(__fadd_rn(__fadd_rn(__fmul_rn(Rb[3], p0), __fmul_rn(Rb[4], p1)),
                                  __fmul_rn(Rb[5], p2)), tb[1]);
    float Z = __fadd_rn(__fadd_rn(__fadd_rn(__fmul_rn(Rb[6], p0), __fmul_rn(Rb[7], p1)),
                                  __fmul_rn(Rb[8], p2)), tb[2]);

    float zs = fmaxf(Z, 1e-6f);
    float xs = __fdiv_rn(X, zs);
    float ys = __fdiv_rn(Y, zs);

    float u = __fadd_rn(__fadd_rn(__fmul_rn(Kb[0], xs), __fmul_rn(Kb[1], ys)), Kb[2]);
    float v = __fadd_rn(__fadd_rn(__fmul_rn(Kb[3], xs), __fmul_rn(Kb[4], ys)), Kb[5]);
    float fx = Kb[0];
    float fy = Kb[4];

    float sxx = cov[3 * gid + 0];
    float syy = cov[3 * gid + 1];
    float sx = __fdiv_rn(__fmul_rn(__fsqrt_rn(fmaxf(sxx, 1e-9f)), fx), zs);
    float sy = __fdiv_rn(__fmul_rn(__fsqrt_rn(fmaxf(syy, 1e-9f)), fy), zs);

    float o  = opa[gid];
    float cr = rgb[3 * gid + 0];
    float cg = rgb[3 * gid + 1];
    float cb = rgb[3 * gid + 2];

    __half2 h_rg = __floats2half2_rn(cr, cg);
    __half2 h_bz = __floats2half2_rn(cb, Z);

    float isx = __fdiv_rn(1.f, fmaxf(sx, 1e-6f));
    float isy = __fdiv_rn(1.f, fmaxf(sy, 1e-6f));

    float wxm[KTAP], wyo[KTAP];
    int   xoff[KTAP], yrow[KTAP];
#pragma unroll
    for (int i = 0; i < KTAP; ++i) {
        float off = (float)(i - KTAP / 2);
        float gx = __fmul_rn(off, isx);
        float gy = __fmul_rn(off, isy);
        float ewx = __expf(-0.5f * __fmul_rn(gx, gx));
        float ewy = __expf(-0.5f * __fmul_rn(gy, gy));
        int px = __float2int_rn(__fadd_rn(u, __fmul_rn(off, sx)));
        int py = __float2int_rn(__fadd_rn(v, __fmul_rn(off, sy)));
        bool okx = (px >= 0) & (px < W);
        bool oky = (py >= 0) & (py < H);
        wxm[i] = okx ? ewx : 0.f;
        wyo[i] = oky ? __fmul_rn(ewy, o) : 0.f;
        xoff[i] = px * 16;
        yrow[i] = py * W * 16;
    }

    char* baseb = (char*)g_acc + (size_t)b * (H * W) * 16;
#pragma unroll
    for (int j = 0; j < KTAP; ++j) {
        float wj = wyo[j];
        if (wj == 0.f) continue;
        char* rowp = baseb + yrow[j];
#pragma unroll
        for (int i = 0; i < KTAP; ++i) {
            float wi = wxm[i];
            if (wi == 0.f) continue;
            float a = __fmul_rn(wi, wj);
            __half2 a2 = __floats2half2_rn(a, a);
            __half2 v0 = __hmul2(h_rg, a2);   // (r*a, g*a)
            __half2 v1 = __hmul2(h_bz, a2);   // (b*a, z*a)
            unsigned r0 = *(unsigned*)&v0;
            unsigned r1 = *(unsigned*)&v1;
            unsigned r2 = *(unsigned*)&a2;    // (a, a) — free
            char* dst = rowp + xoff[i];
            asm volatile("red.global.add.noftz.v4.f16x2 [%0], {%1, %2, %3, %4};"
                         :: "l"(dst), "r"(r0), "r"(r1), "r"(r2), "r"(0u)
                         : "memory");
        }
    }
}

__device__ __forceinline__ void normalize_batch(
    float* __restrict__ out, int b, int B, int HW, int wid, int nw)
{
    int nquad = HW >> 2;
    float* zbase = out + (size_t)B * 3 * HW + (size_t)b * HW;
    float* cbase = out + (size_t)b * 3 * HW;
    for (int q = wid; q < nquad; q += nw) {
        int i0 = q << 2;
        int gbase = b * HW + i0;
        uint4 a0 = g_acc[gbase + 0];
        uint4 a1 = g_acc[gbase + 1];
        uint4 a2 = g_acc[gbase + 2];
        uint4 a3 = g_acc[gbase + 3];

        float4 r4, g4, b4, z4;
        {
            float2 f0 = __half22float2(*(__half2*)&a0.x);
            float2 f1 = __half22float2(*(__half2*)&a0.y);
            float den = fmaxf(__low2float(*(__half2*)&a0.z), 1e-6f);
            float inv; asm("rcp.approx.f32 %0, %1;" : "=f"(inv) : "f"(den));
            r4.x = f0.x * inv; g4.x = f0.y * inv; b4.x = f1.x * inv; z4.x = f1.y * inv;
        }
        {
            float2 f0 = __half22float2(*(__half2*)&a1.x);
            float2 f1 = __half22float2(*(__half2*)&a1.y);
            float den = fmaxf(__low2float(*(__half2*)&a1.z), 1e-6f);
            float inv; asm("rcp.approx.f32 %0, %1;" : "=f"(inv) : "f"(den));
            r4.y = f0.x * inv; g4.y = f0.y * inv; b4.y = f1.x * inv; z4.y = f1.y * inv;
        }
        {
            float2 f0 = __half22float2(*(__half2*)&a2.x);
            float2 f1 = __half22float2(*(__half2*)&a2.y);
            float den = fmaxf(__low2float(*(__half2*)&a2.z), 1e-6f);
            float inv; asm("rcp.approx.f32 %0, %1;" : "=f"(inv) : "f"(den));
            r4.z = f0.x * inv; g4.z = f0.y * inv; b4.z = f1.x * inv; z4.z = f1.y * inv;
        }
        {
            float2 f0 = __half22float2(*(__half2*)&a3.x);
            float2 f1 = __half22float2(*(__half2*)&a3.y);
            float den = fmaxf(__low2float(*(__half2*)&a3.z), 1e-6f);
            float inv; asm("rcp.approx.f32 %0, %1;" : "=f"(inv) : "f"(den));
            r4.w = f0.x * inv; g4.w = f0.y * inv; b4.w = f1.x * inv; z4.w = f1.y * inv;
        }

        *(float4*)(cbase + i0)          = r4;
        *(float4*)(cbase + HW + i0)     = g4;
        *(float4*)(cbase + 2 * HW + i0) = b4;
        *(float4*)(zbase + i0)          = z4;
    }
}

__global__ void __launch_bounds__(NTHR, 3)
render_kernel(const float* __restrict__ pos, const float* __restrict__ cov,
              const float* __restrict__ rgb, const float* __restrict__ opa,
              const float* __restrict__ Km,  const float* __restrict__ Rm,
              const float* __restrict__ tv,  float* __restrict__ out,
              int B, int N, int H, int W)
{
    int tx  = threadIdx.x;
    int bx  = blockIdx.x;
    int gid = bx * NTHR + tx;
    int HW  = H * W;

    unsigned target = g_gen_v + 1u;

    zero_batch(0, HW, gid, NBLK * NTHR);
    grid_sync(target);

    // contiguous per-block gaussian chunk (coalesced input loads, all SMs active)
    int g0 = (int)(((long long)N * bx) / NBLK);
    int g1 = (int)(((long long)N * (bx + 1)) / NBLK);

    for (int b = 0; b < B; ++b) {
        if (tx < SPLAT_THR) {
            for (int g = g0 + tx; g < g1; g += SPLAT_THR)
                splat_one(pos, cov, rgb, opa, Km, Rm, tv, b, b * N + g, H, W);
        } else if (tx < NORM_BASE) {
            if (b + 1 < B) {
                int wid = bx * ZERO_THR + (tx - ZERO_BASE);
                zero_batch(b + 1, HW, wid, NBLK * ZERO_THR);
            }
        } else {
            if (b > 0) {
                int wid = bx * NORM_THR + (tx - NORM_BASE);
                normalize_batch(out, b - 1, B, HW, wid, NBLK * NORM_THR);
            }
        }
        grid_sync(target);
    }

    normalize_batch(out, B - 1, B, HW, gid, NBLK * NTHR);
}

extern "C" void kernel_launch(void* const* d_in, const int* in_sizes, int n_in,
                              void* d_out, int out_size)
{
    const float* pos = (const float*)d_in[0];
    const float* cov = (const float*)d_in[1];
    const float* rgb = (const float*)d_in[2];
    const float* opa = (const float*)d_in[3];
    const float* Km  = (const float*)d_in[4];
    const float* Rm  = (const float*)d_in[5];
    const float* tv  = (const float*)d_in[6];

    int B  = in_sizes[4] / 9;
    int N  = in_sizes[0] / (3 * B);
    int HW = out_size / (4 * B);
    int W  = (int)(sqrt((double)HW) + 0.5);
    int H  = HW / W;

    render_kernel<<<NBLK, NTHR>>>(pos, cov, rgb, opa, Km, Rm, tv,
                                  (float*)d_out, B, N, H, W);
}

// round 12
// speedup vs baseline: 1.2640x; 1.1382x over previous
#include <cuda_runtime.h>
#include <cuda_fp16.h>
#include <math.h>

// ---------------------------------------------------------------------------
// GaussianSplatRenderer3D — B=4, N=32768, H=W=512, k=11 (121 taps)
// Serial 3-kernel pipeline (measured-best structure):
//   zero (STG.128 stream) -> splat (ONE red.global.add.noftz.v4.f16x2 per
//   tap; at the REDG lane floor ~62us) -> normalize (x4, ldcs/stcs, rcp.approx)
// Persistent / warp-specialized variants measured 105-117us: rejected.
// ---------------------------------------------------------------------------

#define KTAP 11
#define MAXPIX (4 * 512 * 512)

static __device__ uint4 g_acc[MAXPIX];   // 8 x f16 per pixel

__global__ void zero_kernel(int npix) {
    int i = blockIdx.x * blockDim.x + threadIdx.x;
    if (i < npix)
        g_acc[i] = make_uint4(0u, 0u, 0u, 0u);
}

__global__ void __launch_bounds__(128)
splat_kernel(const float* __restrict__ pos, const float* __restrict__ cov,
             const float* __restrict__ rgb, const float* __restrict__ opa,
             const float* __restrict__ Km,  const float* __restrict__ Rm,
             const float* __restrict__ tv,  int B, int N, int H, int W)
{
    int gid = blockIdx.x * blockDim.x + threadIdx.x;
    if (gid >= B * N) return;
    int b = gid / N;

    const float* Kb = Km + 9 * b;
    const float* Rb = Rm + 9 * b;
    const float* tb = tv + 3 * b;

    float p0 = pos[3 * gid + 0];
    float p1 = pos[3 * gid + 1];
    float p2 = pos[3 * gid + 2];

    // Xc = R @ p + t  (mul/add chain, no FMA contraction — matches XLA dot)
    float X = __fadd_rn(__fadd_rn(__fadd_rn(__fmul_rn(Rb[0], p0), __fmul_rn(Rb[1], p1)),
                                  __fmul_rn(Rb[2], p2)), tb[0]);
    float Y = __fadd_rn(__fadd_rn(__fadd_rn(__fmul_rn(Rb[3], p0), __fmul_rn(Rb[4], p1)),
                                  __fmul_rn(Rb[5], p2)), tb[1]);
    float Z = __fadd_rn(__fadd_rn(__fadd_rn(__fmul_rn(Rb[6], p0), __fmul_rn(Rb[7], p1)),
                                  __fmul_rn(Rb[8], p2)), tb[2]);

    float zs = fmaxf(Z, 1e-6f);
    float xs = __fdiv_rn(X, zs);
    float ys = __fdiv_rn(Y, zs);

    float u = __fadd_rn(__fadd_rn(__fmul_rn(Kb[0], xs), __fmul_rn(Kb[1], ys)), Kb[2]);
    float v = __fadd_rn(__fadd_rn(__fmul_rn(Kb[3], xs), __fmul_rn(Kb[4], ys)), Kb[5]);
    float fx = Kb[0];
    float fy = Kb[4];

    float sxx = cov[3 * gid + 0];
    float syy = cov[3 * gid + 1];
    float sx = __fdiv_rn(__fmul_rn(__fsqrt_rn(fmaxf(sxx, 1e-9f)), fx), zs);
    float sy = __fdiv_rn(__fmul_rn(__fsqrt_rn(fmaxf(syy, 1e-9f)), fy), zs);

    float o  = opa[gid];
    float cr = rgb[3 * gid + 0];
    float cg = rgb[3 * gid + 1];
    float cb = rgb[3 * gid + 2];

    // Packed per-gaussian constants: slot0 scale (r,g), slot1 scale (b,z)
    __half2 h_rg = __floats2half2_rn(cr, cg);
    __half2 h_bz = __floats2half2_rn(cb, Z);

    float isx = __fdiv_rn(1.f, fmaxf(sx, 1e-6f));
    float isy = __fdiv_rn(1.f, fmaxf(sy, 1e-6f));

    // Per-axis weights (0 for OOB -> tap skipped) and byte offsets
    float wxm[KTAP], wyo[KTAP];
    int   xoff[KTAP], yrow[KTAP];
#pragma unroll
    for (int i = 0; i < KTAP; ++i) {
        float off = (float)(i - KTAP / 2);
        float gx = __fmul_rn(off, isx);
        float gy = __fmul_rn(off, isy);
        float ewx = __expf(-0.5f * __fmul_rn(gx, gx));
        float ewy = __expf(-0.5f * __fmul_rn(gy, gy));
        int px = __float2int_rn(__fadd_rn(u, __fmul_rn(off, sx)));
        int py = __float2int_rn(__fadd_rn(v, __fmul_rn(off, sy)));
        bool okx = (px >= 0) & (px < W);
        bool oky = (py >= 0) & (py < H);
        wxm[i] = okx ? ewx : 0.f;
        wyo[i] = oky ? __fmul_rn(ewy, o) : 0.f;
        xoff[i] = px * 16;
        yrow[i] = py * W * 16;
    }

    char* baseb = (char*)g_acc + (size_t)b * (H * W) * 16;
#pragma unroll
    for (int j = 0; j < KTAP; ++j) {
        float wj = wyo[j];
        if (wj == 0.f) continue;
        char* rowp = baseb + yrow[j];
#pragma unroll
        for (int i = 0; i < KTAP; ++i) {
            float wi = wxm[i];
            if (wi == 0.f) continue;
            float a = __fmul_rn(wi, wj);
            __half2 a2 = __floats2half2_rn(a, a);
            __half2 v0 = __hmul2(h_rg, a2);   // (r*a, g*a)
            __half2 v1 = __hmul2(h_bz, a2);   // (b*a, z*a)
            unsigned r0 = *(unsigned*)&v0;
            unsigned r1 = *(unsigned*)&v1;
            unsigned r2 = *(unsigned*)&a2;    // (a, a) — free
            char* dst = rowp + xoff[i];
            asm volatile("red.global.add.noftz.v4.f16x2 [%0], {%1, %2, %3, %4};"
                         :: "l"(dst), "r"(r0), "r"(r1), "r"(r2), "r"(0u)
                         : "memory");
        }
    }
}

// x4 pixels/thread; streaming loads (evict-first) of the dead accumulator,
// streaming stores of the write-once output; rcp.approx for the divide.
__global__ void __launch_bounds__(256)
normalize_kernel(float* __restrict__ out, int B, int H, int W) {
    int HW = H * W;
    int t = blockIdx.x * blockDim.x + threadIdx.x;   // quad index
    int nquad = (B * HW) >> 2;
    if (t >= nquad) return;
    int i0 = t << 2;

    uint4 a0 = __ldcs(&g_acc[i0 + 0]);
    uint4 a1 = __ldcs(&g_acc[i0 + 1]);
    uint4 a2 = __ldcs(&g_acc[i0 + 2]);
    uint4 a3 = __ldcs(&g_acc[i0 + 3]);

    int b   = i0 / HW;
    int pix = i0 - b * HW;

    float4 r4, g4, b4, z4;
    {
        float2 f0 = __half22float2(*(__half2*)&a0.x);
        float2 f1 = __half22float2(*(__half2*)&a0.y);
        float den = fmaxf(__low2float(*(__half2*)&a0.z), 1e-6f);
        float inv; asm("rcp.approx.f32 %0, %1;" : "=f"(inv) : "f"(den));
        r4.x = f0.x * inv; g4.x = f0.y * inv; b4.x = f1.x * inv; z4.x = f1.y * inv;
    }
    {
        float2 f0 = __half22float2(*(__half2*)&a1.x);
        float2 f1 = __half22float2(*(__half2*)&a1.y);
        float den = fmaxf(__low2float(*(__half2*)&a1.z), 1e-6f);
        float inv; asm("rcp.approx.f32 %0, %1;" : "=f"(inv) : "f"(den));
        r4.y = f0.x * inv; g4.y = f0.y * inv; b4.y = f1.x * inv; z4.y = f1.y * inv;
    }
    {
        float2 f0 = __half22float2(*(__half2*)&a2.x);
        float2 f1 = __half22float2(*(__half2*)&a2.y);
        float den = fmaxf(__low2float(*(__half2*)&a2.z), 1e-6f);
        float inv; asm("rcp.approx.f32 %0, %1;" : "=f"(inv) : "f"(den));
        r4.z = f0.x * inv; g4.z = f0.y * inv; b4.z = f1.x * inv; z4.z = f1.y * inv;
    }
    {
        float2 f0 = __half22float2(*(__half2*)&a3.x);
        float2 f1 = __half22float2(*(__half2*)&a3.y);
        float den = fmaxf(__low2float(*(__half2*)&a3.z), 1e-6f);
        float inv; asm("rcp.approx.f32 %0, %1;" : "=f"(inv) : "f"(den));
        r4.w = f0.x * inv; g4.w = f0.y * inv; b4.w = f1.x * inv; z4.w = f1.y * inv;
    }

    float* rgbout = out + (size_t)b * 3 * HW + pix;
    __stcs((float4*)(rgbout),          r4);
    __stcs((float4*)(rgbout + HW),     g4);
    __stcs((float4*)(rgbout + 2 * HW), b4);
    __stcs((float4*)(out + (size_t)B * 3 * HW + (size_t)b * HW + pix), z4);
}

extern "C" void kernel_launch(void* const* d_in, const int* in_sizes, int n_in,
                              void* d_out, int out_size)
{
    const float* pos = (const float*)d_in[0];
    const float* cov = (const float*)d_in[1];
    const float* rgb = (const float*)d_in[2];
    const float* opa = (const float*)d_in[3];
    const float* Km  = (const float*)d_in[4];
    const float* Rm  = (const float*)d_in[5];
    const float* tv  = (const float*)d_in[6];

    int B  = in_sizes[4] / 9;
    int N  = in_sizes[0] / (3 * B);
    int HW = out_size / (4 * B);
    int W  = (int)(sqrt((double)HW) + 0.5);
    int H  = HW / W;
    int npix = B * HW;

    zero_kernel<<<(npix + 255) / 256, 256>>>(npix);

    int total = B * N;
    splat_kernel<<<(total + 127) / 128, 128>>>(pos, cov, rgb, opa, Km, Rm, tv, B, N, H, W);

    int nquad = npix >> 2;
    normalize_kernel<<<(nquad + 255) / 256, 256>>>((float*)d_out, B, H, W);
}